// round 1
// baseline (speedup 1.0000x reference)
#include <cuda_runtime.h>
#include <cuda_bf16.h>

// Problem constants
#define B_      4
#define CIN     256
#define HH      32
#define WW      88
#define HW      2816            // 32*88
#define PTOT    11264           // B_*HW
#define COUT    128             // context channels only (softmax-mean == 1/64, depth branch dead)
#define OUTH    432
#define OUTW    496
#define XVEC    124             // 496/4
#define NVEC    27426816u       // 4*128*432*124

// Scratch: context tensor [B][COUT][HW], already scaled by 1/64 and biased.
__device__ float g_ctx[B_ * COUT * HW];

// ---------------------------------------------------------------------------
// Kernel 1: GEMM  ctx[b,c,hw] = (sum_k feat[b,k,hw] * Wc[64+c,k] + bc[64+c]) / 64
// Block tile: 32 positions x 128 channels, K-step 16. 256 threads.
// Thread tile: 4 channels x 4 positions (16 accumulators).
// ---------------------------------------------------------------------------
__global__ __launch_bounds__(256, 4)
void lss_gemm_kernel(const float* __restrict__ feat,
                     const float* __restrict__ Wc,
                     const float* __restrict__ bc)
{
    __shared__ float Ws[16][COUT];   // [k][c]  8KB
    __shared__ float Fs[16][32];     // [k][p]  2KB

    const int tid = threadIdx.x;
    const int p0  = blockIdx.x * 32;            // 2816 % 32 == 0 -> never crosses batch
    const int b   = p0 / HW;
    const int hw0 = p0 - b * HW;

    const int cy = (tid >> 3) << 2;             // channel base (0..124, step 4)
    const int px = (tid & 7) << 2;              // position base (0..28, step 4)

    float acc[4][4];
#pragma unroll
    for (int i = 0; i < 4; i++)
#pragma unroll
        for (int j = 0; j < 4; j++) acc[i][j] = 0.0f;

    const float* featb = feat + (size_t)b * CIN * HW + hw0;

    for (int k0 = 0; k0 < CIN; k0 += 16) {
        // Load W tile: 16k x 128c = 2048 floats, 8 per thread
#pragma unroll
        for (int it = 0; it < 8; it++) {
            int i = tid + it * 256;
            int c = i >> 4;
            int k = i & 15;
            Ws[k][c] = Wc[(64 + c) * CIN + k0 + k];
        }
        // Load F tile: 16k x 32p = 512 floats, 2 per thread
#pragma unroll
        for (int it = 0; it < 2; it++) {
            int i = tid + it * 256;
            int k = i >> 5;
            int p = i & 31;
            Fs[k][p] = featb[(size_t)(k0 + k) * HW + p];
        }
        __syncthreads();

#pragma unroll
        for (int k = 0; k < 16; k++) {
            float4 w = *(const float4*)&Ws[k][cy];
            float4 f = *(const float4*)&Fs[k][px];
            acc[0][0] += w.x * f.x; acc[0][1] += w.x * f.y; acc[0][2] += w.x * f.z; acc[0][3] += w.x * f.w;
            acc[1][0] += w.y * f.x; acc[1][1] += w.y * f.y; acc[1][2] += w.y * f.z; acc[1][3] += w.y * f.w;
            acc[2][0] += w.z * f.x; acc[2][1] += w.z * f.y; acc[2][2] += w.z * f.z; acc[2][3] += w.z * f.w;
            acc[3][0] += w.w * f.x; acc[3][1] += w.w * f.y; acc[3][2] += w.w * f.z; acc[3][3] += w.w * f.w;
        }
        __syncthreads();
    }

    const float inv64 = 1.0f / 64.0f;
#pragma unroll
    for (int cc = 0; cc < 4; cc++) {
        int c = cy + cc;
        float bias = bc[64 + c];
        float* dst = g_ctx + ((size_t)(b * COUT + c)) * HW + hw0 + px;
        float4 v;
        v.x = (acc[cc][0] + bias) * inv64;
        v.y = (acc[cc][1] + bias) * inv64;
        v.z = (acc[cc][2] + bias) * inv64;
        v.w = (acc[cc][3] + bias) * inv64;
        *(float4*)dst = v;
    }
}

// ---------------------------------------------------------------------------
// Kernel 2: bilinear upsample (jax.image.resize 'bilinear' semantics:
// half-pixel centers, clamp to edge). Each thread writes one float4 along X.
// ---------------------------------------------------------------------------
__global__ __launch_bounds__(256)
void lss_upsample_kernel(float* __restrict__ out)
{
    unsigned gid = blockIdx.x * 256u + threadIdx.x;
    if (gid >= NVEC) return;

    unsigned xv    = gid % XVEC;
    unsigned t     = gid / XVEC;
    unsigned Y     = t % OUTH;
    unsigned plane = t / OUTH;        // b*128 + c, 0..511

    const float SY = 32.0f / 432.0f;
    const float OY = 0.5f * 32.0f / 432.0f - 0.5f;
    const float SX = 88.0f / 496.0f;
    const float OX = 0.5f * 88.0f / 496.0f - 0.5f;

    float fy = fminf(fmaxf((float)Y * SY + OY, 0.0f), 31.0f);
    int   y0 = (int)fy;
    float wy = fy - (float)y0;
    int   y1 = min(y0 + 1, HH - 1);

    const float* base = g_ctx + (size_t)plane * HW;
    const float* r0 = base + y0 * WW;
    const float* r1 = base + y1 * WW;

    float X0 = (float)(xv * 4u);
    float o[4];
#pragma unroll
    for (int j = 0; j < 4; j++) {
        float fx = fminf(fmaxf((X0 + (float)j) * SX + OX, 0.0f), 87.0f);
        int   x0 = (int)fx;
        float wx = fx - (float)x0;
        int   x1 = min(x0 + 1, WW - 1);
        float a0 = r0[x0], a1 = r0[x1];
        float b0 = r1[x0], b1 = r1[x1];
        float top = a0 + wx * (a1 - a0);
        float bot = b0 + wx * (b1 - b0);
        o[j] = top + wy * (bot - top);
    }
    ((float4*)out)[gid] = make_float4(o[0], o[1], o[2], o[3]);
}

extern "C" void kernel_launch(void* const* d_in, const int* in_sizes, int n_in,
                              void* d_out, int out_size)
{
    const float* feat = (const float*)d_in[0];   // [4,256,32,88]
    const float* Wc   = (const float*)d_in[1];   // [192,256]
    const float* bc   = (const float*)d_in[2];   // [192]
    float* out        = (float*)d_out;           // [4,128,432,496]

    lss_gemm_kernel<<<PTOT / 32, 256>>>(feat, Wc, bc);

    unsigned nblk = (NVEC + 255u) / 256u;
    lss_upsample_kernel<<<nblk, 256>>>(out);
}

// round 2
// speedup vs baseline: 1.3685x; 1.3685x over previous
#include <cuda_runtime.h>
#include <cuda_bf16.h>

#define B_      4
#define CIN     256
#define HH      32
#define WW      88
#define HW      2816
#define PTOT    11264
#define COUT    128
#define OUTH    432
#define OUTW    496
#define XVEC    124             // 496/4
#define NPLANE  512             // B_*COUT
#define YTILE   27              // 432 = 16*27
#define NYT     16

// Scratch: context tensor [plane][HW], scaled by 1/64 and biased.
__device__ float g_ctx[NPLANE * HW];

// ---------------------------------------------------------------------------
// Kernel 1: GEMM  ctx[b,c,hw] = (sum_k feat[b,k,hw]*Wc[64+c,k] + bc[64+c])/64
// Block: 16 positions x 128 channels. 256 threads, thread tile 4c x 2p.
// 704 blocks -> good SM balance.
// ---------------------------------------------------------------------------
__global__ __launch_bounds__(256, 6)
void lss_gemm_kernel(const float* __restrict__ feat,
                     const float* __restrict__ Wc,
                     const float* __restrict__ bc)
{
    __shared__ float Ws[16][COUT];   // 8KB
    __shared__ float Fs[16][16];     // 1KB

    const int tid = threadIdx.x;
    const int p0  = blockIdx.x * 16;
    const int b   = p0 / HW;
    const int hw0 = p0 - b * HW;

    const int cy = (tid >> 3) << 2;   // 0..124 step 4
    const int px = (tid & 7) << 1;    // 0..14 step 2

    float acc[4][2];
#pragma unroll
    for (int i = 0; i < 4; i++) { acc[i][0] = 0.f; acc[i][1] = 0.f; }

    const float* featb = feat + (size_t)b * CIN * HW + hw0;

    for (int k0 = 0; k0 < CIN; k0 += 16) {
#pragma unroll
        for (int it = 0; it < 8; it++) {
            int i = tid + it * 256;
            int c = i >> 4, k = i & 15;
            Ws[k][c] = Wc[(64 + c) * CIN + k0 + k];
        }
        {
            int k = tid >> 4, p = tid & 15;
            Fs[k][p] = featb[(size_t)(k0 + k) * HW + p];
        }
        __syncthreads();

#pragma unroll
        for (int k = 0; k < 16; k++) {
            float4 w = *(const float4*)&Ws[k][cy];
            float2 f = *(const float2*)&Fs[k][px];
            acc[0][0] += w.x * f.x; acc[0][1] += w.x * f.y;
            acc[1][0] += w.y * f.x; acc[1][1] += w.y * f.y;
            acc[2][0] += w.z * f.x; acc[2][1] += w.z * f.y;
            acc[3][0] += w.w * f.x; acc[3][1] += w.w * f.y;
        }
        __syncthreads();
    }

    const float inv64 = 1.0f / 64.0f;
#pragma unroll
    for (int cc = 0; cc < 4; cc++) {
        int c = cy + cc;
        float bias = bc[64 + c];
        float2 v;
        v.x = (acc[cc][0] + bias) * inv64;
        v.y = (acc[cc][1] + bias) * inv64;
        *(float2*)&g_ctx[((size_t)(b * COUT + c)) * HW + hw0 + px] = v;
    }
}

// ---------------------------------------------------------------------------
// Kernel 2: separable bilinear upsample.
// Block = (ytile, plane). 27 output rows need <=4 consecutive source rows.
// Phase A: load 4 raw rows (88 f32) to smem.
// Phase B: horizontal interp -> hrow[4][496] smem.
// Phase C: vertical interp, 1 fma lerp per element, float4 stores.
// ---------------------------------------------------------------------------
__global__ __launch_bounds__(128)
void lss_upsample_kernel(float* __restrict__ out)
{
    __shared__ float raw[4][WW];       // 1.4KB
    __shared__ float hrow[4][OUTW];    // 7.75KB

    const int tid   = threadIdx.x;
    const int t     = blockIdx.x;      // ytile 0..15
    const int plane = blockIdx.y;      // 0..511

    const float SY = 32.0f / 432.0f;
    const float OY = 16.0f / 432.0f - 0.5f;
    const float SX = 88.0f / 496.0f;
    const float OX = 44.0f / 496.0f - 0.5f;

    const int rbase = max(2 * t - 1, 0);

    // Phase A: raw source rows (clamped)
    const float* cbase = g_ctx + (size_t)plane * HW;
    for (int i = tid; i < 4 * WW; i += 128) {
        int r = i / WW, x = i - r * WW;
        int ry = min(rbase + r, HH - 1);
        raw[r][x] = cbase[ry * WW + x];
    }
    __syncthreads();

    // Phase B: horizontal interpolation (pad loop to 512 per row)
    for (int i = tid; i < 4 * 512; i += 128) {
        int r = i >> 9, X = i & 511;
        if (X < OUTW) {
            float fx = fminf(fmaxf((float)X * SX + OX, 0.0f), 87.0f);
            int   x0 = (int)fx;
            float wx = fx - (float)x0;
            int   x1 = min(x0 + 1, WW - 1);
            float a = raw[r][x0];
            hrow[r][X] = fmaf(wx, raw[r][x1] - a, a);
        }
    }
    __syncthreads();

    // Phase C: vertical interpolation, one float4 column per thread
    if (tid < XVEC) {
        float4* orow = (float4*)out + (size_t)plane * OUTH * XVEC + tid;
        const int Y0 = t * YTILE;
#pragma unroll 9
        for (int yy = 0; yy < YTILE; yy++) {
            int Y = Y0 + yy;
            float fy = fminf(fmaxf((float)Y * SY + OY, 0.0f), 31.0f);
            int   y0 = (int)fy;
            float wy = fy - (float)y0;
            int   i0 = y0 - rbase;
            int   i1 = min(i0 + 1, 3);
            float4 a = *(const float4*)&hrow[i0][tid << 2];
            float4 b = *(const float4*)&hrow[i1][tid << 2];
            float4 o;
            o.x = fmaf(wy, b.x - a.x, a.x);
            o.y = fmaf(wy, b.y - a.y, a.y);
            o.z = fmaf(wy, b.z - a.z, a.z);
            o.w = fmaf(wy, b.w - a.w, a.w);
            orow[(size_t)Y * XVEC] = o;
        }
    }
}

extern "C" void kernel_launch(void* const* d_in, const int* in_sizes, int n_in,
                              void* d_out, int out_size)
{
    const float* feat = (const float*)d_in[0];
    const float* Wc   = (const float*)d_in[1];
    const float* bc   = (const float*)d_in[2];
    float* out        = (float*)d_out;

    lss_gemm_kernel<<<PTOT / 16, 256>>>(feat, Wc, bc);

    dim3 grid(NYT, NPLANE);
    lss_upsample_kernel<<<grid, 128>>>(out);
}

// round 3
// speedup vs baseline: 1.6330x; 1.1933x over previous
#include <cuda_runtime.h>
#include <cuda_bf16.h>

#define B_      4
#define CIN     256
#define HH      32
#define WW      88
#define HW      2816
#define PTOT    11264
#define COUT    128
#define OUTH    432
#define OUTW    496
#define XVEC    124             // 496/4
#define NPLANE  512
#define YTILE   54              // 432 = 8*54
#define NYT     8
#define SROWS   6               // source rows per ytile (span 4 + edges)

__device__ float g_ctx[NPLANE * HW];

// ---------------------------------------------------------------------------
// Kernel 1: GEMM, full-K-resident smem, barrier-free mainloop.
// Block: 64 channels (half) x 32 positions, 128 threads, thread tile 4c x 4p.
// Smem: Ws[256][64] 64KB + Fs[256][32] 32KB = 96KB dynamic.
// ---------------------------------------------------------------------------
__global__ __launch_bounds__(128)
void lss_gemm_kernel(const float* __restrict__ feat,
                     const float* __restrict__ Wc,
                     const float* __restrict__ bc)
{
    extern __shared__ float sm[];
    float* Ws = sm;                 // [k][c], stride 64
    float* Fs = sm + CIN * 64;      // [k][p], stride 32

    const int tid   = threadIdx.x;
    const int lane  = tid & 31;
    const int wid   = tid >> 5;
    const int p0    = blockIdx.x * 32;
    const int b     = p0 / HW;
    const int hw0   = p0 - b * HW;
    const int cbase = blockIdx.y * 64;          // 0 or 64

    // ---- Fill Ws: transpose Wc[64+cbase+c][k] -> Ws[k][c] ----
    // warp w: c-block = (w&1)*32 + lane, kv window = (w>>1)*32 .. +31
    {
        const float4* Wc4 = (const float4*)Wc;
        int c   = ((wid & 1) << 5) + lane;
        int kv0 = (wid >> 1) << 5;
        const float4* src = Wc4 + (size_t)(64 + cbase + c) * 64 + kv0;
#pragma unroll 4
        for (int kv = 0; kv < 32; kv++) {
            float4 w4 = src[kv];
            int k = (kv0 + kv) << 2;
            Ws[(k + 0) * 64 + c] = w4.x;
            Ws[(k + 1) * 64 + c] = w4.y;
            Ws[(k + 2) * 64 + c] = w4.z;
            Ws[(k + 3) * 64 + c] = w4.w;
        }
    }

    // ---- Fill Fs: direct vector copy feat[b][k][hw0..+31] -> Fs[k][p] ----
    {
        const float4* f4 = (const float4*)(feat + (size_t)b * CIN * HW + hw0);
        // feat row stride = HW/4 = 704 float4
#pragma unroll
        for (int it = 0; it < 16; it++) {
            int i  = tid + it * 128;
            int k  = i >> 3;
            int pv = i & 7;
            ((float4*)Fs)[k * 8 + pv] = f4[(size_t)k * 704 + pv];
        }
    }
    __syncthreads();

    // ---- Mainloop: 256 k, no barriers ----
    const int cy = (tid >> 3) << 2;     // 0..60 (broadcast within warp)
    const int px = (tid & 7) << 2;      // 0..28

    float acc[4][4];
#pragma unroll
    for (int i = 0; i < 4; i++)
#pragma unroll
        for (int j = 0; j < 4; j++) acc[i][j] = 0.0f;

#pragma unroll 8
    for (int k = 0; k < CIN; k++) {
        float4 w = *(const float4*)&Ws[k * 64 + cy];
        float4 f = *(const float4*)&Fs[k * 32 + px];
        acc[0][0] = fmaf(w.x, f.x, acc[0][0]); acc[0][1] = fmaf(w.x, f.y, acc[0][1]);
        acc[0][2] = fmaf(w.x, f.z, acc[0][2]); acc[0][3] = fmaf(w.x, f.w, acc[0][3]);
        acc[1][0] = fmaf(w.y, f.x, acc[1][0]); acc[1][1] = fmaf(w.y, f.y, acc[1][1]);
        acc[1][2] = fmaf(w.y, f.z, acc[1][2]); acc[1][3] = fmaf(w.y, f.w, acc[1][3]);
        acc[2][0] = fmaf(w.z, f.x, acc[2][0]); acc[2][1] = fmaf(w.z, f.y, acc[2][1]);
        acc[2][2] = fmaf(w.z, f.z, acc[2][2]); acc[2][3] = fmaf(w.z, f.w, acc[2][3]);
        acc[3][0] = fmaf(w.w, f.x, acc[3][0]); acc[3][1] = fmaf(w.w, f.y, acc[3][1]);
        acc[3][2] = fmaf(w.w, f.z, acc[3][2]); acc[3][3] = fmaf(w.w, f.w, acc[3][3]);
    }

    const float inv64 = 1.0f / 64.0f;
#pragma unroll
    for (int ci = 0; ci < 4; ci++) {
        int cg = cbase + cy + ci;
        float bias = bc[64 + cg];
        float4 v;
        v.x = (acc[ci][0] + bias) * inv64;
        v.y = (acc[ci][1] + bias) * inv64;
        v.z = (acc[ci][2] + bias) * inv64;
        v.w = (acc[ci][3] + bias) * inv64;
        *(float4*)&g_ctx[((size_t)(b * COUT + cg)) * HW + hw0 + px] = v;
    }
}

// ---------------------------------------------------------------------------
// Kernel 2: separable bilinear upsample, ytile=54 (6 source rows).
// ---------------------------------------------------------------------------
__global__ __launch_bounds__(128)
void lss_upsample_kernel(float* __restrict__ out)
{
    __shared__ float raw[SROWS][WW];
    __shared__ float hrow[SROWS][OUTW];
    __shared__ float ywy[YTILE];
    __shared__ int   yi0[YTILE];
    __shared__ int   yi1[YTILE];

    const int tid   = threadIdx.x;
    const int t     = blockIdx.x;      // 0..7
    const int plane = blockIdx.y;      // 0..511

    const float SY = 32.0f / 432.0f;
    const float OY = 16.0f / 432.0f - 0.5f;
    const float SX = 88.0f / 496.0f;
    const float OX = 44.0f / 496.0f - 0.5f;

    const int rbase = max(4 * t - 1, 0);

    // y-table (uniform per row)
    if (tid < YTILE) {
        int Y = t * YTILE + tid;
        float fy = fminf(fmaxf((float)Y * SY + OY, 0.0f), 31.0f);
        int   y0 = (int)fy;
        ywy[tid] = fy - (float)y0;
        yi0[tid] = y0 - rbase;
        yi1[tid] = min(y0 + 1, HH - 1) - rbase;
    }

    // Phase A: load 6 source rows (clamped)
    const float* cbase = g_ctx + (size_t)plane * HW;
    for (int i = tid; i < SROWS * WW; i += 128) {
        int r = i / WW, x = i - r * WW;
        int ry = min(rbase + r, HH - 1);
        raw[r][x] = cbase[ry * WW + x];
    }
    __syncthreads();

    // Phase B: horizontal interp -> hrow
    for (int i = tid; i < SROWS * 512; i += 128) {
        int r = i >> 9, X = i & 511;
        if (X < OUTW) {
            float fx = fminf(fmaxf((float)X * SX + OX, 0.0f), 87.0f);
            int   x0 = (int)fx;
            float wx = fx - (float)x0;
            int   x1 = min(x0 + 1, WW - 1);
            float a = raw[r][x0];
            hrow[r][X] = fmaf(wx, raw[r][x1] - a, a);
        }
    }
    __syncthreads();

    // Phase C: vertical interp, streaming float4 stores
    if (tid < XVEC) {
        float4* orow = (float4*)out + (size_t)plane * OUTH * XVEC
                       + (size_t)(t * YTILE) * XVEC + tid;
        const int xo = tid << 2;
#pragma unroll 6
        for (int yy = 0; yy < YTILE; yy++) {
            float wy = ywy[yy];
            float4 a = *(const float4*)&hrow[yi0[yy]][xo];
            float4 b = *(const float4*)&hrow[yi1[yy]][xo];
            float4 o;
            o.x = fmaf(wy, b.x - a.x, a.x);
            o.y = fmaf(wy, b.y - a.y, a.y);
            o.z = fmaf(wy, b.z - a.z, a.z);
            o.w = fmaf(wy, b.w - a.w, a.w);
            __stcs(orow, o);
            orow += XVEC;
        }
    }
}

extern "C" void kernel_launch(void* const* d_in, const int* in_sizes, int n_in,
                              void* d_out, int out_size)
{
    const float* feat = (const float*)d_in[0];
    const float* Wc   = (const float*)d_in[1];
    const float* bc   = (const float*)d_in[2];
    float* out        = (float*)d_out;

    const int gemm_smem = CIN * 64 * 4 + CIN * 32 * 4;   // 98304 B
    cudaFuncSetAttribute(lss_gemm_kernel,
                         cudaFuncAttributeMaxDynamicSharedMemorySize, gemm_smem);

    dim3 ggrid(PTOT / 32, 2);
    lss_gemm_kernel<<<ggrid, 128, gemm_smem>>>(feat, Wc, bc);

    dim3 ugrid(NYT, NPLANE);
    lss_upsample_kernel<<<ugrid, 128>>>(out);
}

// round 4
// speedup vs baseline: 2.1023x; 1.2873x over previous
#include <cuda_runtime.h>
#include <cuda_bf16.h>

#define B_      4
#define CIN     256
#define HH      32
#define WW      88
#define HW      2816
#define PTOT    11264
#define COUT    128
#define OUTH    432
#define OUTW    496
#define XVEC    124             // 496/4
#define NPLANE  512
#define YTILE   54              // 432 = 8*54
#define NYT     8
#define SROWS   6

#define KC      32              // GEMM k-chunk
#define PB      64              // positions per block
#define CB      64              // channels per block

__device__ float g_ctx[NPLANE * HW];
__device__ float g_WcT[CIN * COUT];   // [k][c], pre-scaled by 1/64

// ---------------------------------------------------------------------------
// Kernel 0: transpose + scale weight slice: WcT[k][c] = Wc[64+c][k] / 64
// ---------------------------------------------------------------------------
__global__ __launch_bounds__(256)
void lss_prep_kernel(const float* __restrict__ Wc)
{
    int i = blockIdx.x * 256 + threadIdx.x;   // 32768 total
    int k = i >> 7, c = i & 127;
    g_WcT[i] = Wc[(64 + c) * CIN + k] * (1.0f / 64.0f);
}

// ---------------------------------------------------------------------------
// Kernel 1: GEMM ctx[b,c,hw] = sum_k feat[b,k,hw]*WcT[k][c] + bc[64+c]/64
// Block 64c x 64p, 128 threads, thread tile 8c x 4p, double-buffered KC=32.
// Grid 176 x 2 = 352 blocks (one fully-resident wave).
// ---------------------------------------------------------------------------
__global__ __launch_bounds__(128)
void lss_gemm_kernel(const float* __restrict__ feat,
                     const float* __restrict__ bc)
{
    __shared__ float Ws[2][KC * CB];   // 16KB
    __shared__ float Fs[2][KC * PB];   // 16KB

    const int tid   = threadIdx.x;
    const int p0    = blockIdx.x * PB;
    const int b     = p0 / HW;
    const int hw0   = p0 - b * HW;
    const int cbase = blockIdx.y * CB;          // 0 or 64

    const float4* WcT4  = (const float4*)g_WcT;        // row stride 32
    const float4* feat4 = (const float4*)(feat + (size_t)b * CIN * HW + hw0); // row stride 704

    const int lkk = tid >> 4;        // 0..7  (k within chunk, +8 per iter)
    const int lcv = tid & 15;        // float4 col 0..15

    float4 wreg[4], freg[4];

    // prologue: load chunk 0
#pragma unroll
    for (int it = 0; it < 4; it++) {
        int kk = lkk + it * 8;
        wreg[it] = WcT4[(size_t)kk * 32 + (cbase >> 2) + lcv];
        freg[it] = feat4[(size_t)kk * 704 + lcv];
    }
#pragma unroll
    for (int it = 0; it < 4; it++) {
        int kk = lkk + it * 8;
        ((float4*)Ws[0])[kk * 16 + lcv] = wreg[it];
        ((float4*)Fs[0])[kk * 16 + lcv] = freg[it];
    }
    __syncthreads();

    const int cy = (tid >> 4) << 3;   // 0..56
    const int px = (tid & 15) << 2;   // 0..60

    float acc[8][4];
#pragma unroll
    for (int i = 0; i < 8; i++)
#pragma unroll
        for (int j = 0; j < 4; j++) acc[i][j] = 0.0f;

    int buf = 0;
    for (int ch = 0; ch < CIN / KC; ch++) {
        if (ch < CIN / KC - 1) {
            int k0 = (ch + 1) * KC;
#pragma unroll
            for (int it = 0; it < 4; it++) {
                int kk = k0 + lkk + it * 8;
                wreg[it] = WcT4[(size_t)kk * 32 + (cbase >> 2) + lcv];
                freg[it] = feat4[(size_t)kk * 704 + lcv];
            }
        }

        const float* Wsb = Ws[buf];
        const float* Fsb = Fs[buf];
#pragma unroll 16
        for (int k = 0; k < KC; k++) {
            float4 w0 = *(const float4*)&Wsb[k * CB + cy];
            float4 w1 = *(const float4*)&Wsb[k * CB + cy + 4];
            float4 f  = *(const float4*)&Fsb[k * PB + px];
            acc[0][0] = fmaf(w0.x, f.x, acc[0][0]); acc[0][1] = fmaf(w0.x, f.y, acc[0][1]);
            acc[0][2] = fmaf(w0.x, f.z, acc[0][2]); acc[0][3] = fmaf(w0.x, f.w, acc[0][3]);
            acc[1][0] = fmaf(w0.y, f.x, acc[1][0]); acc[1][1] = fmaf(w0.y, f.y, acc[1][1]);
            acc[1][2] = fmaf(w0.y, f.z, acc[1][2]); acc[1][3] = fmaf(w0.y, f.w, acc[1][3]);
            acc[2][0] = fmaf(w0.z, f.x, acc[2][0]); acc[2][1] = fmaf(w0.z, f.y, acc[2][1]);
            acc[2][2] = fmaf(w0.z, f.z, acc[2][2]); acc[2][3] = fmaf(w0.z, f.w, acc[2][3]);
            acc[3][0] = fmaf(w0.w, f.x, acc[3][0]); acc[3][1] = fmaf(w0.w, f.y, acc[3][1]);
            acc[3][2] = fmaf(w0.w, f.z, acc[3][2]); acc[3][3] = fmaf(w0.w, f.w, acc[3][3]);
            acc[4][0] = fmaf(w1.x, f.x, acc[4][0]); acc[4][1] = fmaf(w1.x, f.y, acc[4][1]);
            acc[4][2] = fmaf(w1.x, f.z, acc[4][2]); acc[4][3] = fmaf(w1.x, f.w, acc[4][3]);
            acc[5][0] = fmaf(w1.y, f.x, acc[5][0]); acc[5][1] = fmaf(w1.y, f.y, acc[5][1]);
            acc[5][2] = fmaf(w1.y, f.z, acc[5][2]); acc[5][3] = fmaf(w1.y, f.w, acc[5][3]);
            acc[6][0] = fmaf(w1.z, f.x, acc[6][0]); acc[6][1] = fmaf(w1.z, f.y, acc[6][1]);
            acc[6][2] = fmaf(w1.z, f.z, acc[6][2]); acc[6][3] = fmaf(w1.z, f.w, acc[6][3]);
            acc[7][0] = fmaf(w1.w, f.x, acc[7][0]); acc[7][1] = fmaf(w1.w, f.y, acc[7][1]);
            acc[7][2] = fmaf(w1.w, f.z, acc[7][2]); acc[7][3] = fmaf(w1.w, f.w, acc[7][3]);
        }

        if (ch < CIN / KC - 1) {
            int nb = buf ^ 1;
#pragma unroll
            for (int it = 0; it < 4; it++) {
                int kk = lkk + it * 8;
                ((float4*)Ws[nb])[kk * 16 + lcv] = wreg[it];
                ((float4*)Fs[nb])[kk * 16 + lcv] = freg[it];
            }
            __syncthreads();
            buf = nb;
        }
    }

    const float inv64 = 1.0f / 64.0f;
#pragma unroll
    for (int ci = 0; ci < 8; ci++) {
        int cg = cbase + cy + ci;
        float bias = bc[64 + cg] * inv64;
        float4 v;
        v.x = acc[ci][0] + bias;
        v.y = acc[ci][1] + bias;
        v.z = acc[ci][2] + bias;
        v.w = acc[ci][3] + bias;
        *(float4*)&g_ctx[((size_t)(b * COUT + cg)) * HW + hw0 + px] = v;
    }
}

// ---------------------------------------------------------------------------
// Kernel 2: separable bilinear upsample, segment-cached vertical pass.
// ---------------------------------------------------------------------------
__global__ __launch_bounds__(128)
void lss_upsample_kernel(float* __restrict__ out)
{
    __shared__ float raw[SROWS][WW];
    __shared__ float hrow[SROWS][OUTW];
    __shared__ float ywy[YTILE];
    __shared__ int   yi0s[YTILE];

    const int tid   = threadIdx.x;
    const int t     = blockIdx.x;      // 0..7
    const int plane = blockIdx.y;      // 0..511

    const float SY = 32.0f / 432.0f;
    const float OY = 16.0f / 432.0f - 0.5f;
    const float SX = 88.0f / 496.0f;
    const float OX = 44.0f / 496.0f - 0.5f;

    const int rbase = max(4 * t - 1, 0);

    if (tid < YTILE) {
        int Y = t * YTILE + tid;
        float fy = fminf(fmaxf((float)Y * SY + OY, 0.0f), 31.0f);
        int   y0 = (int)fy;
        ywy[tid]  = fy - (float)y0;
        yi0s[tid] = y0 - rbase;        // 0..4, monotone non-decreasing
    }

    // Phase A: load 6 source rows (edge-clamped)
    const float* cbase = g_ctx + (size_t)plane * HW;
    for (int i = tid; i < SROWS * WW; i += 128) {
        int r = i / WW, x = i - r * WW;
        int ry = min(rbase + r, HH - 1);
        raw[r][x] = cbase[ry * WW + x];
    }
    __syncthreads();

    // Phase B: horizontal interpolation
    for (int i = tid; i < SROWS * 512; i += 128) {
        int r = i >> 9, X = i & 511;
        if (X < OUTW) {
            float fx = fminf(fmaxf((float)X * SX + OX, 0.0f), 87.0f);
            int   x0 = (int)fx;
            float wx = fx - (float)x0;
            int   x1 = min(x0 + 1, WW - 1);
            float a = raw[r][x0];
            hrow[r][X] = fmaf(wx, raw[r][x1] - a, a);
        }
    }
    __syncthreads();

    // Phase C: vertical pass. For each source-row segment, cache the two
    // hrows in registers; inner loop = 4 FMA + 1 streaming STG.128.
    if (tid < XVEC) {
        const int xo = tid << 2;
        float4* orow = (float4*)out + (size_t)plane * OUTH * XVEC
                       + (size_t)(t * YTILE) * XVEC + tid;
        int yy = 0;
#pragma unroll
        for (int r = 0; r < 5; r++) {
            float4 a = *(const float4*)&hrow[r][xo];
            float4 b = *(const float4*)&hrow[r + 1][xo];
            float4 d;
            d.x = b.x - a.x; d.y = b.y - a.y; d.z = b.z - a.z; d.w = b.w - a.w;
            while (yy < YTILE && yi0s[yy] == r) {
                float wy = ywy[yy];
                float4 o;
                o.x = fmaf(wy, d.x, a.x);
                o.y = fmaf(wy, d.y, a.y);
                o.z = fmaf(wy, d.z, a.z);
                o.w = fmaf(wy, d.w, a.w);
                __stcs(orow, o);
                orow += XVEC;
                yy++;
            }
        }
    }
}

extern "C" void kernel_launch(void* const* d_in, const int* in_sizes, int n_in,
                              void* d_out, int out_size)
{
    const float* feat = (const float*)d_in[0];
    const float* Wc   = (const float*)d_in[1];
    const float* bc   = (const float*)d_in[2];
    float* out        = (float*)d_out;

    lss_prep_kernel<<<CIN * COUT / 256, 256>>>(Wc);

    dim3 ggrid(PTOT / PB, 2);
    lss_gemm_kernel<<<ggrid, 128>>>(feat, bc);

    dim3 ugrid(NYT, NPLANE);
    lss_upsample_kernel<<<ugrid, 128>>>(out);
}